// round 1
// baseline (speedup 1.0000x reference)
#include <cuda_runtime.h>
#include <cstdint>

#define SDIM  16
#define NNODE 256
#define VDIM  64
#define EDIM  64
#define HDIM  16
#define KEDGE 255   // N-1

// per-node projections: pr[n] = v0[n] @ we1[0:64], psb[n] = v0[n] @ we1[64:128] + be1
__device__ float g_pr [SDIM * NNODE * HDIM];
__device__ float g_psb[SDIM * NNODE * HDIM];

__device__ __forceinline__ float fast_tanh(float x) {
    // tanh(x) = 1 - 2/(e^{2x}+1); robust at +/-inf, MUFU-based
    float y = __expf(2.0f * x);
    return 1.0f - __fdividef(2.0f, y + 1.0f);
}

// ---------------------------------------------------------------------------
// Kernel 1: one block per (s,n).
//   ev = sum_k e0[s,n,k,:]            (the 267MB read)
//   dv = tanh(ev@wv1+bv1)@wv2+bv2     -> out
//   pr, psb per node                   -> scratch
// ---------------------------------------------------------------------------
__global__ void __launch_bounds__(256) node_kernel(
    const float* __restrict__ v0,
    const float* __restrict__ e0,
    const float* __restrict__ wv1, const float* __restrict__ bv1,
    const float* __restrict__ wv2, const float* __restrict__ bv2,
    const float* __restrict__ we1, const float* __restrict__ be1,
    float* __restrict__ dv_out)
{
    const int sn  = blockIdx.x;           // s*256 + n
    const int tid = threadIdx.x;          // 256 threads

    __shared__ float4 part[16][17];       // [k-group][c4], padded
    __shared__ float  evs[EDIM];
    __shared__ float  vs [VDIM];
    __shared__ float  hv [HDIM];

    // --- phase A: strided float4 reduction of e0 over k ---
    const float4* e0p = reinterpret_cast<const float4*>(e0) + (size_t)sn * (KEDGE * EDIM / 4);
    const int c4 = tid & 15;              // which float4 of the 64-wide channel dim
    const int kg = tid >> 4;              // k-group 0..15
    float4 acc = make_float4(0.f, 0.f, 0.f, 0.f);
    #pragma unroll 4
    for (int k = kg; k < KEDGE; k += 16) {
        float4 v = e0p[k * 16 + c4];
        acc.x += v.x; acc.y += v.y; acc.z += v.z; acc.w += v.w;
    }
    part[kg][c4] = acc;
    __syncthreads();

    if (tid < 16) {
        float4 s = part[0][tid];
        #pragma unroll
        for (int g = 1; g < 16; g++) {
            float4 p = part[g][tid];
            s.x += p.x; s.y += p.y; s.z += p.z; s.w += p.w;
        }
        reinterpret_cast<float4*>(evs)[tid] = s;
    } else if (tid < 32) {
        reinterpret_cast<float4*>(vs)[tid - 16] =
            reinterpret_cast<const float4*>(v0)[sn * 16 + (tid - 16)];
    }
    __syncthreads();

    // --- phase B: tiny per-node matmuls ---
    if (tid < 16) {
        float a = bv1[tid];
        #pragma unroll
        for (int e = 0; e < EDIM; e++) a = fmaf(evs[e], wv1[e * HDIM + tid], a);
        hv[tid] = fast_tanh(a);
    } else if (tid < 32) {
        int j = tid - 16;
        float a = 0.f;
        #pragma unroll
        for (int e = 0; e < VDIM; e++) a = fmaf(vs[e], we1[e * HDIM + j], a);
        g_pr[sn * HDIM + j] = a;
    } else if (tid < 48) {
        int j = tid - 32;
        float a = be1[j];
        #pragma unroll
        for (int e = 0; e < VDIM; e++) a = fmaf(vs[e], we1[(VDIM + e) * HDIM + j], a);
        g_psb[sn * HDIM + j] = a;
    }
    __syncthreads();

    if (tid < VDIM) {
        float a = bv2[tid];
        #pragma unroll
        for (int j = 0; j < HDIM; j++) a = fmaf(hv[j], wv2[j * VDIM + tid], a);
        dv_out[(size_t)sn * VDIM + tid] = a;
    }
}

// ---------------------------------------------------------------------------
// Kernel 2: one block per (s,i). 256 threads = 16 edge-groups x 16 lanes.
// Edge (i,k): j = k + (k>=i);  h = pr[j] + psb[i];  de = tanh(h) @ we2 + be2.
// Lane l owns output channels 4l..4l+3 (2 x f32x2 accumulators, we2 in regs).
// t broadcast via shfl width 16.
// ---------------------------------------------------------------------------
__global__ void __launch_bounds__(256) edge_kernel(
    const float* __restrict__ we2, const float* __restrict__ be2,
    float* __restrict__ de_out)
{
    const int sn  = blockIdx.x;           // s*256 + i
    const int s   = sn >> 8;
    const int i   = sn & 255;
    const int tid = threadIdx.x;
    const int l   = tid & 15;             // lane within group == channel quad
    const int g   = tid >> 4;             // edge group 0..15

    __shared__ float prs[NNODE * HDIM];   // 16 KB: pr for this s

    // stage pr[s, :, :] into smem (coalesced float4)
    {
        const float4* prg  = reinterpret_cast<const float4*>(g_pr + s * NNODE * HDIM);
        float4*       prs4 = reinterpret_cast<float4*>(prs);
        #pragma unroll
        for (int q = 0; q < 4; q++) prs4[tid + 256 * q] = prg[tid + 256 * q];
    }

    const float psb_l = g_psb[sn * HDIM + l];

    // we2 slice for this lane: channels 4l..4l+3, all 16 h-dims, packed f32x2
    unsigned long long w0[16], w1[16];
    #pragma unroll
    for (int e = 0; e < HDIM; e++) {
        float4 w = reinterpret_cast<const float4*>(we2)[e * 16 + l];
        asm("mov.b64 %0, {%1, %2};" : "=l"(w0[e]) : "f"(w.x), "f"(w.y));
        asm("mov.b64 %0, {%1, %2};" : "=l"(w1[e]) : "f"(w.z), "f"(w.w));
    }
    unsigned long long B0, B1;
    {
        float4 b = reinterpret_cast<const float4*>(be2)[l];
        asm("mov.b64 %0, {%1, %2};" : "=l"(B0) : "f"(b.x), "f"(b.y));
        asm("mov.b64 %0, {%1, %2};" : "=l"(B1) : "f"(b.z), "f"(b.w));
    }
    __syncthreads();

    float* outbase = de_out + (size_t)sn * KEDGE * VDIM;

    #pragma unroll 1
    for (int iter = 0; iter < 16; iter++) {
        const int k  = iter * 16 + g;
        const int kc = (k < KEDGE) ? k : (KEDGE - 1);     // clamp for inactive tail
        const int j  = kc + (kc >= i);                    // skip diagonal

        const float x = prs[j * HDIM + l] + psb_l;
        const float t = fast_tanh(x);

        unsigned long long A0 = B0, A1 = B1;
        #pragma unroll
        for (int e = 0; e < HDIM; e++) {
            float tb = __shfl_sync(0xffffffffu, t, e, 16);
            unsigned long long tt;
            asm("mov.b64 %0, {%1, %1};" : "=l"(tt) : "f"(tb));
            asm("fma.rn.f32x2 %0, %1, %2, %0;" : "+l"(A0) : "l"(w0[e]), "l"(tt));
            asm("fma.rn.f32x2 %0, %1, %2, %0;" : "+l"(A1) : "l"(w1[e]), "l"(tt));
        }

        if (k < KEDGE) {
            float4 o;
            asm("mov.b64 {%0, %1}, %2;" : "=f"(o.x), "=f"(o.y) : "l"(A0));
            asm("mov.b64 {%0, %1}, %2;" : "=f"(o.z), "=f"(o.w) : "l"(A1));
            *reinterpret_cast<float4*>(outbase + (size_t)k * VDIM + l * 4) = o;
        }
    }
}

// ---------------------------------------------------------------------------
// inputs (metadata order): t, v0, e0, wv1, bv1, wv2, bv2, we1, be1, we2, be2,
//                          recv_idx, send_idx (idx arrays unused: analytic)
// output: dv (S,N,V) followed by de (S,N,N-1,E)
// ---------------------------------------------------------------------------
extern "C" void kernel_launch(void* const* d_in, const int* in_sizes, int n_in,
                              void* d_out, int out_size)
{
    const float* v0  = (const float*)d_in[1];
    const float* e0  = (const float*)d_in[2];
    const float* wv1 = (const float*)d_in[3];
    const float* bv1 = (const float*)d_in[4];
    const float* wv2 = (const float*)d_in[5];
    const float* bv2 = (const float*)d_in[6];
    const float* we1 = (const float*)d_in[7];
    const float* be1 = (const float*)d_in[8];
    const float* we2 = (const float*)d_in[9];
    const float* be2 = (const float*)d_in[10];

    float* dv_out = (float*)d_out;
    float* de_out = dv_out + (size_t)SDIM * NNODE * VDIM;

    node_kernel<<<SDIM * NNODE, 256>>>(v0, e0, wv1, bv1, wv2, bv2, we1, be1, dv_out);
    edge_kernel<<<SDIM * NNODE, 256>>>(we2, be2, de_out);
}